// round 7
// baseline (speedup 1.0000x reference)
#include <cuda_runtime.h>
#include <cuda_bf16.h>
#include <cstdint>

#define N_NODES 50000
#define N_EDGES 800000
#define NE_TOT  (N_EDGES + N_NODES)   // 850000
#define IN_CH   128
#define OUT_CH  128
#define HEADS   4
#define HEAD_DIM 32
#define NEG_SLOPE 0.2f
#define LN_EPS 1e-5f

#define SCAN_B 512
#define NTILES ((N_NODES + SCAN_B - 1) / SCAN_B)   // 98

// ---------------- scratch ---------------------------------------------------------
__device__ float    g_xl[N_NODES * OUT_CH];
__device__ float    g_xr[N_NODES * OUT_CH];
// W in tf32, pre-swizzled into mma B-fragment order:
// idx = ((((nh*16+ks)*4+tig)*8+gid)*8 + nt)*2 + j   (j: 0 -> k=8ks+tig, 1 -> k=8ks+tig+4)
__device__ uint32_t g_wl32[IN_CH * OUT_CH];
__device__ uint32_t g_wr32[IN_CH * OUT_CH];
__device__ int      g_cnt[N_NODES];
__device__ int      g_fill[N_NODES];
__device__ int      g_rowptr[N_NODES + 1];
__device__ int      g_csr[NE_TOT];
__device__ int      g_scan_agg[NTILES];
__device__ int      g_scan_pref[NTILES];
__device__ volatile int g_scan_flag[NTILES];

__device__ __forceinline__ float lrelu(float f) {
    return f > 0.f ? f : NEG_SLOPE * f;
}

__device__ __forceinline__ uint32_t f2tf32(float v) {
    uint32_t r;
    asm("cvt.rna.tf32.f32 %0, %1;" : "=r"(r) : "f"(v));
    return r;
}

// ---------------- kernel A: convert + swizzle W to fragment order -------------------
__global__ void k_wconv(const float* __restrict__ Wl, const float* __restrict__ Wr) {
    int i = blockIdx.x * blockDim.x + threadIdx.x;
    if (i >= IN_CH * OUT_CH) return;
    int k = i >> 7, n = i & 127;
    int ks = k >> 3, kr = k & 7;
    int tig = kr & 3, j = kr >> 2;
    int nh = n >> 6, nt = (n >> 3) & 7, gid = n & 7;
    int pidx = (((((nh * 16 + ks) * 4 + tig) * 8 + gid) * 8) + nt) * 2 + j;
    g_wl32[pidx] = f2tf32(Wl[i]);
    g_wr32[pidx] = f2tf32(Wr[i]);
}

// ---------------- kernel 0: init counters + scan flags ------------------------------
__global__ void k_init() {
    int i = blockIdx.x * blockDim.x + threadIdx.x;
    if (i < N_NODES) {
        g_cnt[i] = 1;      // self loop pre-counted
        g_fill[i] = 0;
    }
    if (i < NTILES) {
        g_scan_flag[i] = 0;
    }
}

// ---------------- kernel 1: histogram of destination degrees ------------------------
__global__ __launch_bounds__(256) void k_hist(const int* __restrict__ ei) {
    int e = blockIdx.x * blockDim.x + threadIdx.x;
    if (e < N_EDGES) atomicAdd(&g_cnt[ei[N_EDGES + e]], 1);
}

// ---------------- kernel 2: dual GEMM via mma.sync tf32, vectorized B feed ----------
// block 512 = 16 warps; 64 nodes/block.
// warp: mat = w>>3, m16-tile = (w>>1)&3, n-half = w&1; per warp m16 x n64 x k128
#define XS_PITCH 132
__global__ __launch_bounds__(512, 2) void k_gemm_mma(
    const float* __restrict__ x,
    const float* __restrict__ bl,
    const float* __restrict__ br)
{
    __shared__ uint32_t xs[64 * XS_PITCH];

    int tid = threadIdx.x;
    int nblk = blockIdx.x * 64;

    // load + convert x tile (64 x 128), coalesced float4
    #pragma unroll
    for (int i = 0; i < 4; i++) {
        int idx = tid + i * 512;
        int r = idx >> 5, c = idx & 31;
        int n = nblk + r;
        float4 v = make_float4(0.f, 0.f, 0.f, 0.f);
        if (n < N_NODES) v = *reinterpret_cast<const float4*>(x + (size_t)n * IN_CH + c * 4);
        uint4 t;
        t.x = f2tf32(v.x); t.y = f2tf32(v.y); t.z = f2tf32(v.z); t.w = f2tf32(v.w);
        *reinterpret_cast<uint4*>(&xs[r * XS_PITCH + c * 4]) = t;
    }
    __syncthreads();

    int wid  = tid >> 5;
    int lane = tid & 31;
    int gid  = lane >> 2;      // 0..7
    int tig  = lane & 3;       // 0..3
    int mat  = wid >> 3;
    int mt   = (wid >> 1) & 3;
    int nh   = wid & 1;

    const uint32_t* W = mat ? g_wr32 : g_wl32;
    // per-warp fragment base: varies only with ks
    // off(ks) = (nh*16+ks)*512 + tig*128 + gid*16
    const uint32_t* Wbase = W + nh * 16 * 512 + tig * 128 + gid * 16;

    float acc[8][4];
    #pragma unroll
    for (int nt = 0; nt < 8; nt++)
        #pragma unroll
        for (int j = 0; j < 4; j++) acc[nt][j] = 0.f;

    int arow0 = (mt * 16 + gid) * XS_PITCH;
    int arow1 = arow0 + 8 * XS_PITCH;
    int nbase = nh * 64;

    #pragma unroll
    for (int ks = 0; ks < 16; ks++) {
        int k0 = ks * 8;
        uint32_t a0 = xs[arow0 + k0 + tig];
        uint32_t a1 = xs[arow1 + k0 + tig];
        uint32_t a2 = xs[arow0 + k0 + tig + 4];
        uint32_t a3 = xs[arow1 + k0 + tig + 4];

        const uint4* bp = reinterpret_cast<const uint4*>(Wbase + ks * 512);
        // first 4 nt
        {
            uint4 q0 = bp[0];   // nt0:{j0,j1}, nt1:{j0,j1}
            uint4 q1 = bp[1];   // nt2, nt3
            asm volatile("mma.sync.aligned.m16n8k8.row.col.f32.tf32.tf32.f32 "
                "{%0,%1,%2,%3}, {%4,%5,%6,%7}, {%8,%9}, {%0,%1,%2,%3};"
                : "+f"(acc[0][0]), "+f"(acc[0][1]), "+f"(acc[0][2]), "+f"(acc[0][3])
                : "r"(a0), "r"(a1), "r"(a2), "r"(a3), "r"(q0.x), "r"(q0.y));
            asm volatile("mma.sync.aligned.m16n8k8.row.col.f32.tf32.tf32.f32 "
                "{%0,%1,%2,%3}, {%4,%5,%6,%7}, {%8,%9}, {%0,%1,%2,%3};"
                : "+f"(acc[1][0]), "+f"(acc[1][1]), "+f"(acc[1][2]), "+f"(acc[1][3])
                : "r"(a0), "r"(a1), "r"(a2), "r"(a3), "r"(q0.z), "r"(q0.w));
            asm volatile("mma.sync.aligned.m16n8k8.row.col.f32.tf32.tf32.f32 "
                "{%0,%1,%2,%3}, {%4,%5,%6,%7}, {%8,%9}, {%0,%1,%2,%3};"
                : "+f"(acc[2][0]), "+f"(acc[2][1]), "+f"(acc[2][2]), "+f"(acc[2][3])
                : "r"(a0), "r"(a1), "r"(a2), "r"(a3), "r"(q1.x), "r"(q1.y));
            asm volatile("mma.sync.aligned.m16n8k8.row.col.f32.tf32.tf32.f32 "
                "{%0,%1,%2,%3}, {%4,%5,%6,%7}, {%8,%9}, {%0,%1,%2,%3};"
                : "+f"(acc[3][0]), "+f"(acc[3][1]), "+f"(acc[3][2]), "+f"(acc[3][3])
                : "r"(a0), "r"(a1), "r"(a2), "r"(a3), "r"(q1.z), "r"(q1.w));
        }
        // last 4 nt
        {
            uint4 q2 = bp[2];   // nt4, nt5
            uint4 q3 = bp[3];   // nt6, nt7
            asm volatile("mma.sync.aligned.m16n8k8.row.col.f32.tf32.tf32.f32 "
                "{%0,%1,%2,%3}, {%4,%5,%6,%7}, {%8,%9}, {%0,%1,%2,%3};"
                : "+f"(acc[4][0]), "+f"(acc[4][1]), "+f"(acc[4][2]), "+f"(acc[4][3])
                : "r"(a0), "r"(a1), "r"(a2), "r"(a3), "r"(q2.x), "r"(q2.y));
            asm volatile("mma.sync.aligned.m16n8k8.row.col.f32.tf32.tf32.f32 "
                "{%0,%1,%2,%3}, {%4,%5,%6,%7}, {%8,%9}, {%0,%1,%2,%3};"
                : "+f"(acc[5][0]), "+f"(acc[5][1]), "+f"(acc[5][2]), "+f"(acc[5][3])
                : "r"(a0), "r"(a1), "r"(a2), "r"(a3), "r"(q2.z), "r"(q2.w));
            asm volatile("mma.sync.aligned.m16n8k8.row.col.f32.tf32.tf32.f32 "
                "{%0,%1,%2,%3}, {%4,%5,%6,%7}, {%8,%9}, {%0,%1,%2,%3};"
                : "+f"(acc[6][0]), "+f"(acc[6][1]), "+f"(acc[6][2]), "+f"(acc[6][3])
                : "r"(a0), "r"(a1), "r"(a2), "r"(a3), "r"(q3.x), "r"(q3.y));
            asm volatile("mma.sync.aligned.m16n8k8.row.col.f32.tf32.tf32.f32 "
                "{%0,%1,%2,%3}, {%4,%5,%6,%7}, {%8,%9}, {%0,%1,%2,%3};"
                : "+f"(acc[7][0]), "+f"(acc[7][1]), "+f"(acc[7][2]), "+f"(acc[7][3])
                : "r"(a0), "r"(a1), "r"(a2), "r"(a3), "r"(q3.z), "r"(q3.w));
        }
    }

    // epilogue: add bias, store float2 pairs
    const float* bv = mat ? br : bl;
    float* dst = mat ? g_xr : g_xl;
    int r0 = nblk + mt * 16 + gid;
    int r1 = r0 + 8;
    bool ok0 = (r0 < N_NODES), ok1 = (r1 < N_NODES);

    #pragma unroll
    for (int nt = 0; nt < 8; nt++) {
        int c = nbase + nt * 8 + 2 * tig;
        float2 b2 = *reinterpret_cast<const float2*>(bv + c);
        if (ok0) {
            float2 o = make_float2(acc[nt][0] + b2.x, acc[nt][1] + b2.y);
            *reinterpret_cast<float2*>(dst + (size_t)r0 * OUT_CH + c) = o;
        }
        if (ok1) {
            float2 o = make_float2(acc[nt][2] + b2.x, acc[nt][3] + b2.y);
            *reinterpret_cast<float2*>(dst + (size_t)r1 * OUT_CH + c) = o;
        }
    }
}

// ---------------- kernel 3: single-pass exclusive scan ------------------------------
__global__ __launch_bounds__(SCAN_B) void k_scan() {
    __shared__ int warp_excl[16];
    __shared__ int s_total;
    __shared__ int s_prev;

    int t = blockIdx.x, tid = threadIdx.x;
    int i = t * SCAN_B + tid;
    int lane = tid & 31, w = tid >> 5;

    int v = (i < N_NODES) ? g_cnt[i] : 0;

    int inc = v;
    #pragma unroll
    for (int off = 1; off < 32; off <<= 1) {
        int n = __shfl_up_sync(0xFFFFFFFFu, inc, off);
        if (lane >= off) inc += n;
    }
    if (lane == 31) warp_excl[w] = inc;
    __syncthreads();

    if (w == 0) {
        int ws = (lane < 16) ? warp_excl[lane] : 0;
        int wi = ws;
        #pragma unroll
        for (int off = 1; off < 16; off <<= 1) {
            int n = __shfl_up_sync(0xFFFFFFFFu, wi, off);
            if (lane >= off) wi += n;
        }
        if (lane < 16) warp_excl[lane] = wi - ws;
        if (lane == 15) s_total = wi;
    }
    __syncthreads();

    int block_total = s_total;
    int excl_in_block = warp_excl[w] + inc - v;

    if (tid == 0) {
        if (t == 0) {
            g_scan_pref[0] = block_total;
            __threadfence();
            g_scan_flag[0] = 2;
            s_prev = 0;
        } else {
            g_scan_agg[t] = block_total;
            __threadfence();
            g_scan_flag[t] = 1;
            int run = 0;
            int p = t - 1;
            while (true) {
                int f;
                do { f = g_scan_flag[p]; } while (f == 0);
                __threadfence();
                if (f == 2) { run += g_scan_pref[p]; break; }
                run += g_scan_agg[p];
                p--;
            }
            g_scan_pref[t] = run + block_total;
            __threadfence();
            g_scan_flag[t] = 2;
            s_prev = run;
        }
    }
    __syncthreads();

    if (i < N_NODES) g_rowptr[i] = s_prev + excl_in_block;
    if (i == N_NODES - 1) g_rowptr[N_NODES] = s_prev + block_total;
}

// ---------------- kernel 4: fill CSR -------------------------------------------------
__global__ __launch_bounds__(256) void k_fill(const int* __restrict__ ei) {
    int t = blockIdx.x * blockDim.x + threadIdx.x;
    if (t >= NE_TOT) return;
    int src, dst;
    if (t < N_EDGES) { src = ei[t]; dst = ei[N_EDGES + t]; }
    else             { src = dst = t - N_EDGES; }
    int pos = g_rowptr[dst] + atomicAdd(&g_fill[dst], 1);
    g_csr[pos] = src;
}

// ---------------- kernel 5: fused aggregate + SiLU + LayerNorm (2-edge unroll) ------
__global__ __launch_bounds__(256) void k_aggregate(
    const float* __restrict__ att,
    const float* __restrict__ bias,
    const float* __restrict__ gamma,
    const float* __restrict__ beta,
    float* __restrict__ out)
{
    int warp = (blockIdx.x * blockDim.x + threadIdx.x) >> 5;
    int lane = threadIdx.x & 31;
    if (warp >= N_NODES) return;

    float4 a   = *reinterpret_cast<const float4*>(att + lane * 4);
    float4 xr4 = *reinterpret_cast<const float4*>(g_xr + (size_t)warp * OUT_CH + lane * 4);

    int base = g_rowptr[warp];
    int end  = g_rowptr[warp + 1];

    float4 acc = make_float4(0.f, 0.f, 0.f, 0.f);
    float denom = 0.f;

    int k = base;
    for (; k + 1 < end; k += 2) {
        int s0 = g_csr[k];
        int s1 = g_csr[k + 1];
        float4 v0 = *reinterpret_cast<const float4*>(g_xl + (size_t)s0 * OUT_CH + lane * 4);
        float4 v1 = *reinterpret_cast<const float4*>(g_xl + (size_t)s1 * OUT_CH + lane * 4);

        float sc0 = a.x * lrelu(v0.x + xr4.x) + a.y * lrelu(v0.y + xr4.y)
                  + a.z * lrelu(v0.z + xr4.z) + a.w * lrelu(v0.w + xr4.w);
        float sc1 = a.x * lrelu(v1.x + xr4.x) + a.y * lrelu(v1.y + xr4.y)
                  + a.z * lrelu(v1.z + xr4.z) + a.w * lrelu(v1.w + xr4.w);

        sc0 += __shfl_xor_sync(0xFFFFFFFFu, sc0, 1);
        sc1 += __shfl_xor_sync(0xFFFFFFFFu, sc1, 1);
        sc0 += __shfl_xor_sync(0xFFFFFFFFu, sc0, 2);
        sc1 += __shfl_xor_sync(0xFFFFFFFFu, sc1, 2);
        sc0 += __shfl_xor_sync(0xFFFFFFFFu, sc0, 4);
        sc1 += __shfl_xor_sync(0xFFFFFFFFu, sc1, 4);

        float w0 = __expf(sc0);
        float w1 = __expf(sc1);
        denom += w0 + w1;
        acc.x = fmaf(w0, v0.x, fmaf(w1, v1.x, acc.x));
        acc.y = fmaf(w0, v0.y, fmaf(w1, v1.y, acc.y));
        acc.z = fmaf(w0, v0.z, fmaf(w1, v1.z, acc.z));
        acc.w = fmaf(w0, v0.w, fmaf(w1, v1.w, acc.w));
    }
    if (k < end) {
        int s0 = g_csr[k];
        float4 v0 = *reinterpret_cast<const float4*>(g_xl + (size_t)s0 * OUT_CH + lane * 4);
        float sc0 = a.x * lrelu(v0.x + xr4.x) + a.y * lrelu(v0.y + xr4.y)
                  + a.z * lrelu(v0.z + xr4.z) + a.w * lrelu(v0.w + xr4.w);
        sc0 += __shfl_xor_sync(0xFFFFFFFFu, sc0, 1);
        sc0 += __shfl_xor_sync(0xFFFFFFFFu, sc0, 2);
        sc0 += __shfl_xor_sync(0xFFFFFFFFu, sc0, 4);
        float w0 = __expf(sc0);
        denom += w0;
        acc.x = fmaf(w0, v0.x, acc.x);
        acc.y = fmaf(w0, v0.y, acc.y);
        acc.z = fmaf(w0, v0.z, acc.z);
        acc.w = fmaf(w0, v0.w, acc.w);
    }

    float inv = __frcp_rn(denom);
    float4 b = *reinterpret_cast<const float4*>(bias + lane * 4);
    float4 v;
    v.x = fmaf(acc.x, inv, b.x);
    v.y = fmaf(acc.y, inv, b.y);
    v.z = fmaf(acc.z, inv, b.z);
    v.w = fmaf(acc.w, inv, b.w);

    v.x = v.x / (1.f + __expf(-v.x));
    v.y = v.y / (1.f + __expf(-v.y));
    v.z = v.z / (1.f + __expf(-v.z));
    v.w = v.w / (1.f + __expf(-v.w));

    float sum = v.x + v.y + v.z + v.w;
    float sq  = v.x * v.x + v.y * v.y + v.z * v.z + v.w * v.w;
    #pragma unroll
    for (int off = 16; off; off >>= 1) {
        sum += __shfl_xor_sync(0xFFFFFFFFu, sum, off);
        sq  += __shfl_xor_sync(0xFFFFFFFFu, sq,  off);
    }
    float mu   = sum * (1.f / OUT_CH);
    float var  = sq * (1.f / OUT_CH) - mu * mu;
    float rstd = rsqrtf(var + LN_EPS);

    float4 g  = *reinterpret_cast<const float4*>(gamma + lane * 4);
    float4 be = *reinterpret_cast<const float4*>(beta  + lane * 4);
    float4 r;
    r.x = (v.x - mu) * rstd * g.x + be.x;
    r.y = (v.y - mu) * rstd * g.y + be.y;
    r.z = (v.z - mu) * rstd * g.z + be.z;
    r.w = (v.w - mu) * rstd * g.w + be.w;
    *reinterpret_cast<float4*>(out + (size_t)warp * OUT_CH + lane * 4) = r;
}

// ---------------- launcher ------------------------------------------------------------
extern "C" void kernel_launch(void* const* d_in, const int* in_sizes, int n_in,
                              void* d_out, int out_size)
{
    const float* x    = (const float*)d_in[0];
    const int*   ei   = (const int*)  d_in[1];
    const float* Wl   = (const float*)d_in[2];
    const float* bl   = (const float*)d_in[3];
    const float* Wr   = (const float*)d_in[4];
    const float* br   = (const float*)d_in[5];
    const float* att  = (const float*)d_in[6];
    const float* bias = (const float*)d_in[7];
    const float* gam  = (const float*)d_in[8];
    const float* bet  = (const float*)d_in[9];
    float* out = (float*)d_out;

    // order keeps the GEMM at iteration-launch index 3 (ncu capture slot)
    k_wconv<<<(IN_CH * OUT_CH + 255) / 256, 256>>>(Wl, Wr);            // 0
    k_init<<<(N_NODES + 255) / 256, 256>>>();                          // 1
    k_hist<<<(N_EDGES + 255) / 256, 256>>>(ei);                        // 2
    k_gemm_mma<<<(N_NODES + 63) / 64, 512>>>(x, bl, br);               // 3
    k_scan<<<NTILES, SCAN_B>>>();                                      // 4
    k_fill<<<(NE_TOT + 255) / 256, 256>>>(ei);                         // 5
    k_aggregate<<<(N_NODES * 32 + 255) / 256, 256>>>(att, bias, gam, bet, out); // 6
}

// round 8
// speedup vs baseline: 1.1835x; 1.1835x over previous
#include <cuda_runtime.h>
#include <cuda_bf16.h>
#include <cstdint>

#define N_NODES 50000
#define N_EDGES 800000
#define NE_TOT  (N_EDGES + N_NODES)   // 850000
#define IN_CH   128
#define OUT_CH  128
#define HEADS   4
#define HEAD_DIM 32
#define NEG_SLOPE 0.2f
#define LN_EPS 1e-5f

#define SCAN_B 512
#define NTILES ((N_NODES + SCAN_B - 1) / SCAN_B)   // 98

// ---------------- scratch ---------------------------------------------------------
__device__ float    g_xl[N_NODES * OUT_CH];
__device__ float    g_xr[N_NODES * OUT_CH];
// W in tf32, pre-swizzled into mma B-fragment order:
// idx = ((((nh*16+ks)*4+tig)*8+gid)*8 + nt)*2 + j
__device__ uint32_t g_wl32[IN_CH * OUT_CH];
__device__ uint32_t g_wr32[IN_CH * OUT_CH];
__device__ int      g_cnt[N_NODES];
__device__ int      g_fill[N_NODES];
__device__ int      g_rowptr[N_NODES + 1];
__device__ int      g_csr[NE_TOT];
__device__ int      g_scan_agg[NTILES];
__device__ int      g_scan_pref[NTILES];
__device__ volatile int g_scan_flag[NTILES];

__device__ __forceinline__ float lrelu(float f) {
    return f > 0.f ? f : NEG_SLOPE * f;
}

__device__ __forceinline__ uint32_t f2tf32(float v) {
    uint32_t r;
    asm("cvt.rna.tf32.f32 %0, %1;" : "=r"(r) : "f"(v));
    return r;
}

// ---------------- kernel A: convert + swizzle W to fragment order -------------------
__global__ void k_wconv(const float* __restrict__ Wl, const float* __restrict__ Wr) {
    int i = blockIdx.x * blockDim.x + threadIdx.x;
    if (i >= IN_CH * OUT_CH) return;
    int k = i >> 7, n = i & 127;
    int ks = k >> 3, kr = k & 7;
    int tig = kr & 3, j = kr >> 2;
    int nh = n >> 6, nt = (n >> 3) & 7, gid = n & 7;
    int pidx = (((((nh * 16 + ks) * 4 + tig) * 8 + gid) * 8) + nt) * 2 + j;
    g_wl32[pidx] = f2tf32(Wl[i]);
    g_wr32[pidx] = f2tf32(Wr[i]);
}

// ---------------- kernel 0: init counters + scan flags ------------------------------
__global__ void k_init() {
    int i = blockIdx.x * blockDim.x + threadIdx.x;
    if (i < N_NODES) {
        g_cnt[i] = 1;
        g_fill[i] = 0;
    }
    if (i < NTILES) {
        g_scan_flag[i] = 0;
    }
}

// ---------------- kernel 1: histogram of destination degrees ------------------------
__global__ __launch_bounds__(256) void k_hist(const int* __restrict__ ei) {
    int e = blockIdx.x * blockDim.x + threadIdx.x;
    if (e < N_EDGES) atomicAdd(&g_cnt[ei[N_EDGES + e]], 1);
}

// ---------------- kernel 2: dual GEMM, mma.sync tf32, m32-per-warp, 128 regs --------
// block 256 = 8 warps; 64 nodes/block.
// warp: mat = w>>2, nh = (w>>1)&1, mth = w&1 (rows [mth*32, mth*32+32))
// per warp: m32 x n64 x k128 -> acc[2][8][4] = 64 regs
#define XS_PITCH 132
__global__ __launch_bounds__(256, 2) void k_gemm_mma(
    const float* __restrict__ x,
    const float* __restrict__ bl,
    const float* __restrict__ br)
{
    __shared__ uint32_t xs[64 * XS_PITCH];

    int tid = threadIdx.x;
    int nblk = blockIdx.x * 64;

    // load + convert x tile (64 x 128), coalesced float4; 8 per thread
    #pragma unroll
    for (int i = 0; i < 8; i++) {
        int idx = tid + i * 256;
        int r = idx >> 5, c = idx & 31;
        int n = nblk + r;
        float4 v = make_float4(0.f, 0.f, 0.f, 0.f);
        if (n < N_NODES) v = *reinterpret_cast<const float4*>(x + (size_t)n * IN_CH + c * 4);
        uint4 t;
        t.x = f2tf32(v.x); t.y = f2tf32(v.y); t.z = f2tf32(v.z); t.w = f2tf32(v.w);
        *reinterpret_cast<uint4*>(&xs[r * XS_PITCH + c * 4]) = t;
    }
    __syncthreads();

    int wid  = tid >> 5;
    int lane = tid & 31;
    int gid  = lane >> 2;      // 0..7
    int tig  = lane & 3;       // 0..3
    int mat  = wid >> 2;       // 0: Wl, 1: Wr
    int nh   = (wid >> 1) & 1; // n half
    int mth  = wid & 1;        // m half (32 rows)

    const uint32_t* W = mat ? g_wr32 : g_wl32;
    const uint32_t* Wbase = W + nh * 16 * 512 + tig * 128 + gid * 16;

    float acc[2][8][4];
    #pragma unroll
    for (int mt = 0; mt < 2; mt++)
        #pragma unroll
        for (int nt = 0; nt < 8; nt++)
            #pragma unroll
            for (int j = 0; j < 4; j++) acc[mt][nt][j] = 0.f;

    int arowA = (mth * 32 + gid) * XS_PITCH;          // mt=0 rows
    int arowB = arowA + 16 * XS_PITCH;                // mt=1 rows
    int nbase = nh * 64;

    #pragma unroll
    for (int ks = 0; ks < 16; ks++) {
        int k0 = ks * 8;
        const uint4* bp = reinterpret_cast<const uint4*>(Wbase + ks * 512);
        uint4 q0 = bp[0];   // nt0,nt1
        uint4 q1 = bp[1];   // nt2,nt3
        uint4 q2 = bp[2];   // nt4,nt5
        uint4 q3 = bp[3];   // nt6,nt7

        #pragma unroll
        for (int mt = 0; mt < 2; mt++) {
            int ar0 = (mt ? arowB : arowA) + k0 + tig;
            int ar1 = ar0 + 8 * XS_PITCH;
            uint32_t a0 = xs[ar0];
            uint32_t a1 = xs[ar1];
            uint32_t a2 = xs[ar0 + 4];
            uint32_t a3 = xs[ar1 + 4];

            asm volatile("mma.sync.aligned.m16n8k8.row.col.f32.tf32.tf32.f32 "
                "{%0,%1,%2,%3}, {%4,%5,%6,%7}, {%8,%9}, {%0,%1,%2,%3};"
                : "+f"(acc[mt][0][0]), "+f"(acc[mt][0][1]), "+f"(acc[mt][0][2]), "+f"(acc[mt][0][3])
                : "r"(a0), "r"(a1), "r"(a2), "r"(a3), "r"(q0.x), "r"(q0.y));
            asm volatile("mma.sync.aligned.m16n8k8.row.col.f32.tf32.tf32.f32 "
                "{%0,%1,%2,%3}, {%4,%5,%6,%7}, {%8,%9}, {%0,%1,%2,%3};"
                : "+f"(acc[mt][1][0]), "+f"(acc[mt][1][1]), "+f"(acc[mt][1][2]), "+f"(acc[mt][1][3])
                : "r"(a0), "r"(a1), "r"(a2), "r"(a3), "r"(q0.z), "r"(q0.w));
            asm volatile("mma.sync.aligned.m16n8k8.row.col.f32.tf32.tf32.f32 "
                "{%0,%1,%2,%3}, {%4,%5,%6,%7}, {%8,%9}, {%0,%1,%2,%3};"
                : "+f"(acc[mt][2][0]), "+f"(acc[mt][2][1]), "+f"(acc[mt][2][2]), "+f"(acc[mt][2][3])
                : "r"(a0), "r"(a1), "r"(a2), "r"(a3), "r"(q1.x), "r"(q1.y));
            asm volatile("mma.sync.aligned.m16n8k8.row.col.f32.tf32.tf32.f32 "
                "{%0,%1,%2,%3}, {%4,%5,%6,%7}, {%8,%9}, {%0,%1,%2,%3};"
                : "+f"(acc[mt][3][0]), "+f"(acc[mt][3][1]), "+f"(acc[mt][3][2]), "+f"(acc[mt][3][3])
                : "r"(a0), "r"(a1), "r"(a2), "r"(a3), "r"(q1.z), "r"(q1.w));
            asm volatile("mma.sync.aligned.m16n8k8.row.col.f32.tf32.tf32.f32 "
                "{%0,%1,%2,%3}, {%4,%5,%6,%7}, {%8,%9}, {%0,%1,%2,%3};"
                : "+f"(acc[mt][4][0]), "+f"(acc[mt][4][1]), "+f"(acc[mt][4][2]), "+f"(acc[mt][4][3])
                : "r"(a0), "r"(a1), "r"(a2), "r"(a3), "r"(q2.x), "r"(q2.y));
            asm volatile("mma.sync.aligned.m16n8k8.row.col.f32.tf32.tf32.f32 "
                "{%0,%1,%2,%3}, {%4,%5,%6,%7}, {%8,%9}, {%0,%1,%2,%3};"
                : "+f"(acc[mt][5][0]), "+f"(acc[mt][5][1]), "+f"(acc[mt][5][2]), "+f"(acc[mt][5][3])
                : "r"(a0), "r"(a1), "r"(a2), "r"(a3), "r"(q2.z), "r"(q2.w));
            asm volatile("mma.sync.aligned.m16n8k8.row.col.f32.tf32.tf32.f32 "
                "{%0,%1,%2,%3}, {%4,%5,%6,%7}, {%8,%9}, {%0,%1,%2,%3};"
                : "+f"(acc[mt][6][0]), "+f"(acc[mt][6][1]), "+f"(acc[mt][6][2]), "+f"(acc[mt][6][3])
                : "r"(a0), "r"(a1), "r"(a2), "r"(a3), "r"(q3.x), "r"(q3.y));
            asm volatile("mma.sync.aligned.m16n8k8.row.col.f32.tf32.tf32.f32 "
                "{%0,%1,%2,%3}, {%4,%5,%6,%7}, {%8,%9}, {%0,%1,%2,%3};"
                : "+f"(acc[mt][7][0]), "+f"(acc[mt][7][1]), "+f"(acc[mt][7][2]), "+f"(acc[mt][7][3])
                : "r"(a0), "r"(a1), "r"(a2), "r"(a3), "r"(q3.z), "r"(q3.w));
        }
    }

    // epilogue: add bias, store float2 pairs
    const float* bv = mat ? br : bl;
    float* dst = mat ? g_xr : g_xl;

    #pragma unroll
    for (int mt = 0; mt < 2; mt++) {
        int r0 = nblk + mth * 32 + mt * 16 + gid;
        int r1 = r0 + 8;
        bool ok0 = (r0 < N_NODES), ok1 = (r1 < N_NODES);
        #pragma unroll
        for (int nt = 0; nt < 8; nt++) {
            int c = nbase + nt * 8 + 2 * tig;
            float2 b2 = *reinterpret_cast<const float2*>(bv + c);
            if (ok0) {
                float2 o = make_float2(acc[mt][nt][0] + b2.x, acc[mt][nt][1] + b2.y);
                *reinterpret_cast<float2*>(dst + (size_t)r0 * OUT_CH + c) = o;
            }
            if (ok1) {
                float2 o = make_float2(acc[mt][nt][2] + b2.x, acc[mt][nt][3] + b2.y);
                *reinterpret_cast<float2*>(dst + (size_t)r1 * OUT_CH + c) = o;
            }
        }
    }
}

// ---------------- kernel 3: single-pass exclusive scan ------------------------------
__global__ __launch_bounds__(SCAN_B) void k_scan() {
    __shared__ int warp_excl[16];
    __shared__ int s_total;
    __shared__ int s_prev;

    int t = blockIdx.x, tid = threadIdx.x;
    int i = t * SCAN_B + tid;
    int lane = tid & 31, w = tid >> 5;

    int v = (i < N_NODES) ? g_cnt[i] : 0;

    int inc = v;
    #pragma unroll
    for (int off = 1; off < 32; off <<= 1) {
        int n = __shfl_up_sync(0xFFFFFFFFu, inc, off);
        if (lane >= off) inc += n;
    }
    if (lane == 31) warp_excl[w] = inc;
    __syncthreads();

    if (w == 0) {
        int ws = (lane < 16) ? warp_excl[lane] : 0;
        int wi = ws;
        #pragma unroll
        for (int off = 1; off < 16; off <<= 1) {
            int n = __shfl_up_sync(0xFFFFFFFFu, wi, off);
            if (lane >= off) wi += n;
        }
        if (lane < 16) warp_excl[lane] = wi - ws;
        if (lane == 15) s_total = wi;
    }
    __syncthreads();

    int block_total = s_total;
    int excl_in_block = warp_excl[w] + inc - v;

    if (tid == 0) {
        if (t == 0) {
            g_scan_pref[0] = block_total;
            __threadfence();
            g_scan_flag[0] = 2;
            s_prev = 0;
        } else {
            g_scan_agg[t] = block_total;
            __threadfence();
            g_scan_flag[t] = 1;
            int run = 0;
            int p = t - 1;
            while (true) {
                int f;
                do { f = g_scan_flag[p]; } while (f == 0);
                __threadfence();
                if (f == 2) { run += g_scan_pref[p]; break; }
                run += g_scan_agg[p];
                p--;
            }
            g_scan_pref[t] = run + block_total;
            __threadfence();
            g_scan_flag[t] = 2;
            s_prev = run;
        }
    }
    __syncthreads();

    if (i < N_NODES) g_rowptr[i] = s_prev + excl_in_block;
    if (i == N_NODES - 1) g_rowptr[N_NODES] = s_prev + block_total;
}

// ---------------- kernel 4: fill CSR -------------------------------------------------
__global__ __launch_bounds__(256) void k_fill(const int* __restrict__ ei) {
    int t = blockIdx.x * blockDim.x + threadIdx.x;
    if (t >= NE_TOT) return;
    int src, dst;
    if (t < N_EDGES) { src = ei[t]; dst = ei[N_EDGES + t]; }
    else             { src = dst = t - N_EDGES; }
    int pos = g_rowptr[dst] + atomicAdd(&g_fill[dst], 1);
    g_csr[pos] = src;
}

// ---------------- kernel 5: fused aggregate + SiLU + LayerNorm (2-edge unroll) ------
__global__ __launch_bounds__(256) void k_aggregate(
    const float* __restrict__ att,
    const float* __restrict__ bias,
    const float* __restrict__ gamma,
    const float* __restrict__ beta,
    float* __restrict__ out)
{
    int warp = (blockIdx.x * blockDim.x + threadIdx.x) >> 5;
    int lane = threadIdx.x & 31;
    if (warp >= N_NODES) return;

    float4 a   = *reinterpret_cast<const float4*>(att + lane * 4);
    float4 xr4 = *reinterpret_cast<const float4*>(g_xr + (size_t)warp * OUT_CH + lane * 4);

    int base = g_rowptr[warp];
    int end  = g_rowptr[warp + 1];

    float4 acc = make_float4(0.f, 0.f, 0.f, 0.f);
    float denom = 0.f;

    int k = base;
    for (; k + 1 < end; k += 2) {
        int s0 = g_csr[k];
        int s1 = g_csr[k + 1];
        float4 v0 = *reinterpret_cast<const float4*>(g_xl + (size_t)s0 * OUT_CH + lane * 4);
        float4 v1 = *reinterpret_cast<const float4*>(g_xl + (size_t)s1 * OUT_CH + lane * 4);

        float sc0 = a.x * lrelu(v0.x + xr4.x) + a.y * lrelu(v0.y + xr4.y)
                  + a.z * lrelu(v0.z + xr4.z) + a.w * lrelu(v0.w + xr4.w);
        float sc1 = a.x * lrelu(v1.x + xr4.x) + a.y * lrelu(v1.y + xr4.y)
                  + a.z * lrelu(v1.z + xr4.z) + a.w * lrelu(v1.w + xr4.w);

        sc0 += __shfl_xor_sync(0xFFFFFFFFu, sc0, 1);
        sc1 += __shfl_xor_sync(0xFFFFFFFFu, sc1, 1);
        sc0 += __shfl_xor_sync(0xFFFFFFFFu, sc0, 2);
        sc1 += __shfl_xor_sync(0xFFFFFFFFu, sc1, 2);
        sc0 += __shfl_xor_sync(0xFFFFFFFFu, sc0, 4);
        sc1 += __shfl_xor_sync(0xFFFFFFFFu, sc1, 4);

        float w0 = __expf(sc0);
        float w1 = __expf(sc1);
        denom += w0 + w1;
        acc.x = fmaf(w0, v0.x, fmaf(w1, v1.x, acc.x));
        acc.y = fmaf(w0, v0.y, fmaf(w1, v1.y, acc.y));
        acc.z = fmaf(w0, v0.z, fmaf(w1, v1.z, acc.z));
        acc.w = fmaf(w0, v0.w, fmaf(w1, v1.w, acc.w));
    }
    if (k < end) {
        int s0 = g_csr[k];
        float4 v0 = *reinterpret_cast<const float4*>(g_xl + (size_t)s0 * OUT_CH + lane * 4);
        float sc0 = a.x * lrelu(v0.x + xr4.x) + a.y * lrelu(v0.y + xr4.y)
                  + a.z * lrelu(v0.z + xr4.z) + a.w * lrelu(v0.w + xr4.w);
        sc0 += __shfl_xor_sync(0xFFFFFFFFu, sc0, 1);
        sc0 += __shfl_xor_sync(0xFFFFFFFFu, sc0, 2);
        sc0 += __shfl_xor_sync(0xFFFFFFFFu, sc0, 4);
        float w0 = __expf(sc0);
        denom += w0;
        acc.x = fmaf(w0, v0.x, acc.x);
        acc.y = fmaf(w0, v0.y, acc.y);
        acc.z = fmaf(w0, v0.z, acc.z);
        acc.w = fmaf(w0, v0.w, acc.w);
    }

    float inv = __frcp_rn(denom);
    float4 b = *reinterpret_cast<const float4*>(bias + lane * 4);
    float4 v;
    v.x = fmaf(acc.x, inv, b.x);
    v.y = fmaf(acc.y, inv, b.y);
    v.z = fmaf(acc.z, inv, b.z);
    v.w = fmaf(acc.w, inv, b.w);

    v.x = v.x / (1.f + __expf(-v.x));
    v.y = v.y / (1.f + __expf(-v.y));
    v.z = v.z / (1.f + __expf(-v.z));
    v.w = v.w / (1.f + __expf(-v.w));

    float sum = v.x + v.y + v.z + v.w;
    float sq  = v.x * v.x + v.y * v.y + v.z * v.z + v.w * v.w;
    #pragma unroll
    for (int off = 16; off; off >>= 1) {
        sum += __shfl_xor_sync(0xFFFFFFFFu, sum, off);
        sq  += __shfl_xor_sync(0xFFFFFFFFu, sq,  off);
    }
    float mu   = sum * (1.f / OUT_CH);
    float var  = sq * (1.f / OUT_CH) - mu * mu;
    float rstd = rsqrtf(var + LN_EPS);

    float4 g  = *reinterpret_cast<const float4*>(gamma + lane * 4);
    float4 be = *reinterpret_cast<const float4*>(beta  + lane * 4);
    float4 r;
    r.x = (v.x - mu) * rstd * g.x + be.x;
    r.y = (v.y - mu) * rstd * g.y + be.y;
    r.z = (v.z - mu) * rstd * g.z + be.z;
    r.w = (v.w - mu) * rstd * g.w + be.w;
    *reinterpret_cast<float4*>(out + (size_t)warp * OUT_CH + lane * 4) = r;
}

// ---------------- launcher ------------------------------------------------------------
extern "C" void kernel_launch(void* const* d_in, const int* in_sizes, int n_in,
                              void* d_out, int out_size)
{
    const float* x    = (const float*)d_in[0];
    const int*   ei   = (const int*)  d_in[1];
    const float* Wl   = (const float*)d_in[2];
    const float* bl   = (const float*)d_in[3];
    const float* Wr   = (const float*)d_in[4];
    const float* br   = (const float*)d_in[5];
    const float* att  = (const float*)d_in[6];
    const float* bias = (const float*)d_in[7];
    const float* gam  = (const float*)d_in[8];
    const float* bet  = (const float*)d_in[9];
    float* out = (float*)d_out;

    // order keeps the GEMM at iteration-launch index 3 (ncu capture slot)
    k_wconv<<<(IN_CH * OUT_CH + 255) / 256, 256>>>(Wl, Wr);            // 0
    k_init<<<(N_NODES + 255) / 256, 256>>>();                          // 1
    k_hist<<<(N_EDGES + 255) / 256, 256>>>(ei);                        // 2
    k_gemm_mma<<<(N_NODES + 63) / 64, 256>>>(x, bl, br);               // 3
    k_scan<<<NTILES, SCAN_B>>>();                                      // 4
    k_fill<<<(NE_TOT + 255) / 256, 256>>>(ei);                         // 5
    k_aggregate<<<(N_NODES * 32 + 255) / 256, 256>>>(att, bias, gam, bet, out); // 6
}

// round 10
// speedup vs baseline: 1.3233x; 1.1181x over previous
#include <cuda_runtime.h>
#include <cuda_bf16.h>
#include <cstdint>

#define N_NODES 50000
#define N_EDGES 800000
#define NE_TOT  (N_EDGES + N_NODES)   // 850000
#define IN_CH   128
#define OUT_CH  128
#define HEADS   4
#define HEAD_DIM 32
#define NEG_SLOPE 0.2f
#define LN_EPS 1e-5f

#define SCAN_B 512
#define NTILES ((N_NODES + SCAN_B - 1) / SCAN_B)   // 98

// ---------------- scratch ---------------------------------------------------------
__device__ float    g_xl[N_NODES * OUT_CH];
__device__ float    g_xr[N_NODES * OUT_CH];
// W in tf32, pre-swizzled into mma B-fragment order:
// idx = ((((nh*16+ks)*4+tig)*8+gid)*8 + nt)*2 + j
__device__ uint32_t g_wl32[IN_CH * OUT_CH];
__device__ uint32_t g_wr32[IN_CH * OUT_CH];
__device__ int      g_cnt[N_NODES];
__device__ int      g_fill[N_NODES];
__device__ int      g_rowptr[N_NODES + 1];
__device__ int      g_csr[NE_TOT];
__device__ int      g_scan_agg[NTILES];
__device__ int      g_scan_pref[NTILES];
__device__ volatile int g_scan_flag[NTILES];

__device__ __forceinline__ float lrelu(float f) {
    return f > 0.f ? f : NEG_SLOPE * f;
}

__device__ __forceinline__ uint32_t f2tf32(float v) {
    uint32_t r;
    asm("cvt.rna.tf32.f32 %0, %1;" : "=r"(r) : "f"(v));
    return r;
}

// ---------------- kernel A: convert + swizzle W to fragment order -------------------
__global__ void k_wconv(const float* __restrict__ Wl, const float* __restrict__ Wr) {
    int i = blockIdx.x * blockDim.x + threadIdx.x;
    if (i >= IN_CH * OUT_CH) return;
    int k = i >> 7, n = i & 127;
    int ks = k >> 3, kr = k & 7;
    int tig = kr & 3, j = kr >> 2;
    int nh = n >> 6, nt = (n >> 3) & 7, gid = n & 7;
    int pidx = (((((nh * 16 + ks) * 4 + tig) * 8 + gid) * 8) + nt) * 2 + j;
    g_wl32[pidx] = f2tf32(Wl[i]);
    g_wr32[pidx] = f2tf32(Wr[i]);
}

// ---------------- kernel 0: init counters + scan flags ------------------------------
__global__ void k_init() {
    int i = blockIdx.x * blockDim.x + threadIdx.x;
    if (i < N_NODES) {
        g_cnt[i] = 1;
        g_fill[i] = 0;
    }
    if (i < NTILES) {
        g_scan_flag[i] = 0;
    }
}

// ---------------- kernel 1: histogram of destination degrees ------------------------
__global__ __launch_bounds__(256) void k_hist(const int* __restrict__ ei) {
    int e = blockIdx.x * blockDim.x + threadIdx.x;
    if (e < N_EDGES) atomicAdd(&g_cnt[ei[N_EDGES + e]], 1);
}

// ---------------- kernel 2: dual GEMM, mma.sync tf32, m32-per-warp, 128 regs --------
#define XS_PITCH 132
__global__ __launch_bounds__(256, 2) void k_gemm_mma(
    const float* __restrict__ x,
    const float* __restrict__ bl,
    const float* __restrict__ br)
{
    __shared__ uint32_t xs[64 * XS_PITCH];

    int tid = threadIdx.x;
    int nblk = blockIdx.x * 64;

    #pragma unroll
    for (int i = 0; i < 8; i++) {
        int idx = tid + i * 256;
        int r = idx >> 5, c = idx & 31;
        int n = nblk + r;
        float4 v = make_float4(0.f, 0.f, 0.f, 0.f);
        if (n < N_NODES) v = *reinterpret_cast<const float4*>(x + (size_t)n * IN_CH + c * 4);
        uint4 t;
        t.x = f2tf32(v.x); t.y = f2tf32(v.y); t.z = f2tf32(v.z); t.w = f2tf32(v.w);
        *reinterpret_cast<uint4*>(&xs[r * XS_PITCH + c * 4]) = t;
    }
    __syncthreads();

    int wid  = tid >> 5;
    int lane = tid & 31;
    int gid  = lane >> 2;
    int tig  = lane & 3;
    int mat  = wid >> 2;
    int nh   = (wid >> 1) & 1;
    int mth  = wid & 1;

    const uint32_t* W = mat ? g_wr32 : g_wl32;
    const uint32_t* Wbase = W + nh * 16 * 512 + tig * 128 + gid * 16;

    float acc[2][8][4];
    #pragma unroll
    for (int mt = 0; mt < 2; mt++)
        #pragma unroll
        for (int nt = 0; nt < 8; nt++)
            #pragma unroll
            for (int j = 0; j < 4; j++) acc[mt][nt][j] = 0.f;

    int arowA = (mth * 32 + gid) * XS_PITCH;
    int arowB = arowA + 16 * XS_PITCH;
    int nbase = nh * 64;

    #pragma unroll
    for (int ks = 0; ks < 16; ks++) {
        int k0 = ks * 8;
        const uint4* bp = reinterpret_cast<const uint4*>(Wbase + ks * 512);
        uint4 q0 = bp[0];
        uint4 q1 = bp[1];
        uint4 q2 = bp[2];
        uint4 q3 = bp[3];

        #pragma unroll
        for (int mt = 0; mt < 2; mt++) {
            int ar0 = (mt ? arowB : arowA) + k0 + tig;
            int ar1 = ar0 + 8 * XS_PITCH;
            uint32_t a0 = xs[ar0];
            uint32_t a1 = xs[ar1];
            uint32_t a2 = xs[ar0 + 4];
            uint32_t a3 = xs[ar1 + 4];

            asm volatile("mma.sync.aligned.m16n8k8.row.col.f32.tf32.tf32.f32 "
                "{%0,%1,%2,%3}, {%4,%5,%6,%7}, {%8,%9}, {%0,%1,%2,%3};"
                : "+f"(acc[mt][0][0]), "+f"(acc[mt][0][1]), "+f"(acc[mt][0][2]), "+f"(acc[mt][0][3])
                : "r"(a0), "r"(a1), "r"(a2), "r"(a3), "r"(q0.x), "r"(q0.y));
            asm volatile("mma.sync.aligned.m16n8k8.row.col.f32.tf32.tf32.f32 "
                "{%0,%1,%2,%3}, {%4,%5,%6,%7}, {%8,%9}, {%0,%1,%2,%3};"
                : "+f"(acc[mt][1][0]), "+f"(acc[mt][1][1]), "+f"(acc[mt][1][2]), "+f"(acc[mt][1][3])
                : "r"(a0), "r"(a1), "r"(a2), "r"(a3), "r"(q0.z), "r"(q0.w));
            asm volatile("mma.sync.aligned.m16n8k8.row.col.f32.tf32.tf32.f32 "
                "{%0,%1,%2,%3}, {%4,%5,%6,%7}, {%8,%9}, {%0,%1,%2,%3};"
                : "+f"(acc[mt][2][0]), "+f"(acc[mt][2][1]), "+f"(acc[mt][2][2]), "+f"(acc[mt][2][3])
                : "r"(a0), "r"(a1), "r"(a2), "r"(a3), "r"(q1.x), "r"(q1.y));
            asm volatile("mma.sync.aligned.m16n8k8.row.col.f32.tf32.tf32.f32 "
                "{%0,%1,%2,%3}, {%4,%5,%6,%7}, {%8,%9}, {%0,%1,%2,%3};"
                : "+f"(acc[mt][3][0]), "+f"(acc[mt][3][1]), "+f"(acc[mt][3][2]), "+f"(acc[mt][3][3])
                : "r"(a0), "r"(a1), "r"(a2), "r"(a3), "r"(q1.z), "r"(q1.w));
            asm volatile("mma.sync.aligned.m16n8k8.row.col.f32.tf32.tf32.f32 "
                "{%0,%1,%2,%3}, {%4,%5,%6,%7}, {%8,%9}, {%0,%1,%2,%3};"
                : "+f"(acc[mt][4][0]), "+f"(acc[mt][4][1]), "+f"(acc[mt][4][2]), "+f"(acc[mt][4][3])
                : "r"(a0), "r"(a1), "r"(a2), "r"(a3), "r"(q2.x), "r"(q2.y));
            asm volatile("mma.sync.aligned.m16n8k8.row.col.f32.tf32.tf32.f32 "
                "{%0,%1,%2,%3}, {%4,%5,%6,%7}, {%8,%9}, {%0,%1,%2,%3};"
                : "+f"(acc[mt][5][0]), "+f"(acc[mt][5][1]), "+f"(acc[mt][5][2]), "+f"(acc[mt][5][3])
                : "r"(a0), "r"(a1), "r"(a2), "r"(a3), "r"(q2.z), "r"(q2.w));
            asm volatile("mma.sync.aligned.m16n8k8.row.col.f32.tf32.tf32.f32 "
                "{%0,%1,%2,%3}, {%4,%5,%6,%7}, {%8,%9}, {%0,%1,%2,%3};"
                : "+f"(acc[mt][6][0]), "+f"(acc[mt][6][1]), "+f"(acc[mt][6][2]), "+f"(acc[mt][6][3])
                : "r"(a0), "r"(a1), "r"(a2), "r"(a3), "r"(q3.x), "r"(q3.y));
            asm volatile("mma.sync.aligned.m16n8k8.row.col.f32.tf32.tf32.f32 "
                "{%0,%1,%2,%3}, {%4,%5,%6,%7}, {%8,%9}, {%0,%1,%2,%3};"
                : "+f"(acc[mt][7][0]), "+f"(acc[mt][7][1]), "+f"(acc[mt][7][2]), "+f"(acc[mt][7][3])
                : "r"(a0), "r"(a1), "r"(a2), "r"(a3), "r"(q3.z), "r"(q3.w));
        }
    }

    const float* bv = mat ? br : bl;
    float* dst = mat ? g_xr : g_xl;

    #pragma unroll
    for (int mt = 0; mt < 2; mt++) {
        int r0 = nblk + mth * 32 + mt * 16 + gid;
        int r1 = r0 + 8;
        bool ok0 = (r0 < N_NODES), ok1 = (r1 < N_NODES);
        #pragma unroll
        for (int nt = 0; nt < 8; nt++) {
            int c = nbase + nt * 8 + 2 * tig;
            float2 b2 = *reinterpret_cast<const float2*>(bv + c);
            if (ok0) {
                float2 o = make_float2(acc[mt][nt][0] + b2.x, acc[mt][nt][1] + b2.y);
                *reinterpret_cast<float2*>(dst + (size_t)r0 * OUT_CH + c) = o;
            }
            if (ok1) {
                float2 o = make_float2(acc[mt][nt][2] + b2.x, acc[mt][nt][3] + b2.y);
                *reinterpret_cast<float2*>(dst + (size_t)r1 * OUT_CH + c) = o;
            }
        }
    }
}

// ---------------- kernel 3: single-pass exclusive scan ------------------------------
__global__ __launch_bounds__(SCAN_B) void k_scan() {
    __shared__ int warp_excl[16];
    __shared__ int s_total;
    __shared__ int s_prev;

    int t = blockIdx.x, tid = threadIdx.x;
    int i = t * SCAN_B + tid;
    int lane = tid & 31, w = tid >> 5;

    int v = (i < N_NODES) ? g_cnt[i] : 0;

    int inc = v;
    #pragma unroll
    for (int off = 1; off < 32; off <<= 1) {
        int n = __shfl_up_sync(0xFFFFFFFFu, inc, off);
        if (lane >= off) inc += n;
    }
    if (lane == 31) warp_excl[w] = inc;
    __syncthreads();

    if (w == 0) {
        int ws = (lane < 16) ? warp_excl[lane] : 0;
        int wi = ws;
        #pragma unroll
        for (int off = 1; off < 16; off <<= 1) {
            int n = __shfl_up_sync(0xFFFFFFFFu, wi, off);
            if (lane >= off) wi += n;
        }
        if (lane < 16) warp_excl[lane] = wi - ws;
        if (lane == 15) s_total = wi;
    }
    __syncthreads();

    int block_total = s_total;
    int excl_in_block = warp_excl[w] + inc - v;

    if (tid == 0) {
        if (t == 0) {
            g_scan_pref[0] = block_total;
            __threadfence();
            g_scan_flag[0] = 2;
            s_prev = 0;
        } else {
            g_scan_agg[t] = block_total;
            __threadfence();
            g_scan_flag[t] = 1;
            int run = 0;
            int p = t - 1;
            while (true) {
                int f;
                do { f = g_scan_flag[p]; } while (f == 0);
                __threadfence();
                if (f == 2) { run += g_scan_pref[p]; break; }
                run += g_scan_agg[p];
                p--;
            }
            g_scan_pref[t] = run + block_total;
            __threadfence();
            g_scan_flag[t] = 2;
            s_prev = run;
        }
    }
    __syncthreads();

    if (i < N_NODES) g_rowptr[i] = s_prev + excl_in_block;
    if (i == N_NODES - 1) g_rowptr[N_NODES] = s_prev + block_total;
}

// ---------------- kernel 4: fill CSR -------------------------------------------------
__global__ __launch_bounds__(256) void k_fill(const int* __restrict__ ei) {
    int t = blockIdx.x * blockDim.x + threadIdx.x;
    if (t >= NE_TOT) return;
    int src, dst;
    if (t < N_EDGES) { src = ei[t]; dst = ei[N_EDGES + t]; }
    else             { src = dst = t - N_EDGES; }
    int pos = g_rowptr[dst] + atomicAdd(&g_fill[dst], 1);
    g_csr[pos] = src;
}

// ---------------- kernel 5: fused aggregate + SiLU + LayerNorm (2-edge unroll) ------
__global__ __launch_bounds__(256) void k_aggregate(
    const float* __restrict__ att,
    const float* __restrict__ bias,
    const float* __restrict__ gamma,
    const float* __restrict__ beta,
    float* __restrict__ out)
{
    int warp = (blockIdx.x * blockDim.x + threadIdx.x) >> 5;
    int lane = threadIdx.x & 31;
    if (warp >= N_NODES) return;

    float4 a   = *reinterpret_cast<const float4*>(att + lane * 4);
    float4 xr4 = *reinterpret_cast<const float4*>(g_xr + (size_t)warp * OUT_CH + lane * 4);

    int base = g_rowptr[warp];
    int end  = g_rowptr[warp + 1];

    float4 acc = make_float4(0.f, 0.f, 0.f, 0.f);
    float denom = 0.f;

    int k = base;
    for (; k + 1 < end; k += 2) {
        int s0 = g_csr[k];
        int s1 = g_csr[k + 1];
        float4 v0 = *reinterpret_cast<const float4*>(g_xl + (size_t)s0 * OUT_CH + lane * 4);
        float4 v1 = *reinterpret_cast<const float4*>(g_xl + (size_t)s1 * OUT_CH + lane * 4);

        float sc0 = a.x * lrelu(v0.x + xr4.x) + a.y * lrelu(v0.y + xr4.y)
                  + a.z * lrelu(v0.z + xr4.z) + a.w * lrelu(v0.w + xr4.w);
        float sc1 = a.x * lrelu(v1.x + xr4.x) + a.y * lrelu(v1.y + xr4.y)
                  + a.z * lrelu(v1.z + xr4.z) + a.w * lrelu(v1.w + xr4.w);

        sc0 += __shfl_xor_sync(0xFFFFFFFFu, sc0, 1);
        sc1 += __shfl_xor_sync(0xFFFFFFFFu, sc1, 1);
        sc0 += __shfl_xor_sync(0xFFFFFFFFu, sc0, 2);
        sc1 += __shfl_xor_sync(0xFFFFFFFFu, sc1, 2);
        sc0 += __shfl_xor_sync(0xFFFFFFFFu, sc0, 4);
        sc1 += __shfl_xor_sync(0xFFFFFFFFu, sc1, 4);

        float w0 = __expf(sc0);
        float w1 = __expf(sc1);
        denom += w0 + w1;
        acc.x = fmaf(w0, v0.x, fmaf(w1, v1.x, acc.x));
        acc.y = fmaf(w0, v0.y, fmaf(w1, v1.y, acc.y));
        acc.z = fmaf(w0, v0.z, fmaf(w1, v1.z, acc.z));
        acc.w = fmaf(w0, v0.w, fmaf(w1, v1.w, acc.w));
    }
    if (k < end) {
        int s0 = g_csr[k];
        float4 v0 = *reinterpret_cast<const float4*>(g_xl + (size_t)s0 * OUT_CH + lane * 4);
        float sc0 = a.x * lrelu(v0.x + xr4.x) + a.y * lrelu(v0.y + xr4.y)
                  + a.z * lrelu(v0.z + xr4.z) + a.w * lrelu(v0.w + xr4.w);
        sc0 += __shfl_xor_sync(0xFFFFFFFFu, sc0, 1);
        sc0 += __shfl_xor_sync(0xFFFFFFFFu, sc0, 2);
        sc0 += __shfl_xor_sync(0xFFFFFFFFu, sc0, 4);
        float w0 = __expf(sc0);
        denom += w0;
        acc.x = fmaf(w0, v0.x, acc.x);
        acc.y = fmaf(w0, v0.y, acc.y);
        acc.z = fmaf(w0, v0.z, acc.z);
        acc.w = fmaf(w0, v0.w, acc.w);
    }

    float inv = __frcp_rn(denom);
    float4 b = *reinterpret_cast<const float4*>(bias + lane * 4);
    float4 v;
    v.x = fmaf(acc.x, inv, b.x);
    v.y = fmaf(acc.y, inv, b.y);
    v.z = fmaf(acc.z, inv, b.z);
    v.w = fmaf(acc.w, inv, b.w);

    v.x = v.x / (1.f + __expf(-v.x));
    v.y = v.y / (1.f + __expf(-v.y));
    v.z = v.z / (1.f + __expf(-v.z));
    v.w = v.w / (1.f + __expf(-v.w));

    float sum = v.x + v.y + v.z + v.w;
    float sq  = v.x * v.x + v.y * v.y + v.z * v.z + v.w * v.w;
    #pragma unroll
    for (int off = 16; off; off >>= 1) {
        sum += __shfl_xor_sync(0xFFFFFFFFu, sum, off);
        sq  += __shfl_xor_sync(0xFFFFFFFFu, sq,  off);
    }
    float mu   = sum * (1.f / OUT_CH);
    float var  = sq * (1.f / OUT_CH) - mu * mu;
    float rstd = rsqrtf(var + LN_EPS);

    float4 g  = *reinterpret_cast<const float4*>(gamma + lane * 4);
    float4 be = *reinterpret_cast<const float4*>(beta  + lane * 4);
    float4 r;
    r.x = (v.x - mu) * rstd * g.x + be.x;
    r.y = (v.y - mu) * rstd * g.y + be.y;
    r.z = (v.z - mu) * rstd * g.z + be.z;
    r.w = (v.w - mu) * rstd * g.w + be.w;
    *reinterpret_cast<float4*>(out + (size_t)warp * OUT_CH + lane * 4) = r;
}

// ---------------- launcher: two-stream fork/join (capture-legal) --------------------
extern "C" void kernel_launch(void* const* d_in, const int* in_sizes, int n_in,
                              void* d_out, int out_size)
{
    const float* x    = (const float*)d_in[0];
    const int*   ei   = (const int*)  d_in[1];
    const float* Wl   = (const float*)d_in[2];
    const float* bl   = (const float*)d_in[3];
    const float* Wr   = (const float*)d_in[4];
    const float* br   = (const float*)d_in[5];
    const float* att  = (const float*)d_in[6];
    const float* bias = (const float*)d_in[7];
    const float* gam  = (const float*)d_in[8];
    const float* bet  = (const float*)d_in[9];
    float* out = (float*)d_out;

    // created once on the (uncaptured) correctness call; reused during capture
    static cudaStream_t s2 = nullptr;
    static cudaEvent_t  e_fork = nullptr, e_join = nullptr;
    if (s2 == nullptr) {
        cudaStreamCreateWithFlags(&s2, cudaStreamNonBlocking);
        cudaEventCreateWithFlags(&e_fork, cudaEventDisableTiming);
        cudaEventCreateWithFlags(&e_join, cudaEventDisableTiming);
    }

    // fork: CSR-build arm runs on s2, concurrent with GEMM arm on default stream
    cudaEventRecord(e_fork, 0);
    cudaStreamWaitEvent(s2, e_fork, 0);

    // arm B (s2): init -> hist -> scan -> fill   (independent of GEMM)
    k_init<<<(N_NODES + 255) / 256, 256, 0, s2>>>();
    k_hist<<<(N_EDGES + 255) / 256, 256, 0, s2>>>(ei);
    k_scan<<<NTILES, SCAN_B, 0, s2>>>();
    k_fill<<<(NE_TOT + 255) / 256, 256, 0, s2>>>(ei);
    cudaEventRecord(e_join, s2);

    // arm A (default stream): wconv -> GEMM
    k_wconv<<<(IN_CH * OUT_CH + 255) / 256, 256>>>(Wl, Wr);
    k_gemm_mma<<<(N_NODES + 63) / 64, 256>>>(x, bl, br);

    // join, then aggregate (needs both arms)
    cudaStreamWaitEvent(0, e_join, 0);
    k_aggregate<<<(N_NODES * 32 + 255) / 256, 256>>>(att, bias, gam, bet, out);
}

// round 11
// speedup vs baseline: 1.3329x; 1.0073x over previous
#include <cuda_runtime.h>
#include <cuda_bf16.h>
#include <cstdint>

#define N_NODES 50000
#define N_EDGES 800000
#define NE_TOT  (N_EDGES + N_NODES)   // 850000
#define IN_CH   128
#define OUT_CH  128
#define HEADS   4
#define HEAD_DIM 32
#define NEG_SLOPE 0.2f
#define LN_EPS 1e-5f

#define SCAN_B 512
#define NTILES ((N_NODES + SCAN_B - 1) / SCAN_B)   // 98

// ---------------- scratch ---------------------------------------------------------
__device__ float    g_xl[N_NODES * OUT_CH];
__device__ float    g_xr[N_NODES * OUT_CH];
__device__ uint32_t g_wl32[IN_CH * OUT_CH];
__device__ uint32_t g_wr32[IN_CH * OUT_CH];
__device__ int      g_cnt[N_NODES];
__device__ int      g_fill[N_NODES];
__device__ int      g_rowptr[N_NODES + 1];
__device__ int      g_csr[NE_TOT];
__device__ int      g_scan_agg[NTILES];
__device__ int      g_scan_pref[NTILES];
__device__ volatile int g_scan_flag[NTILES];

__device__ __forceinline__ float lrelu(float f) {
    return f > 0.f ? f : NEG_SLOPE * f;
}

__device__ __forceinline__ uint32_t f2tf32(float v) {
    uint32_t r;
    asm("cvt.rna.tf32.f32 %0, %1;" : "=r"(r) : "f"(v));
    return r;
}

// ---------------- kernel A: convert + swizzle W to fragment order -------------------
__global__ void k_wconv(const float* __restrict__ Wl, const float* __restrict__ Wr) {
    int i = blockIdx.x * blockDim.x + threadIdx.x;
    if (i >= IN_CH * OUT_CH) return;
    int k = i >> 7, n = i & 127;
    int ks = k >> 3, kr = k & 7;
    int tig = kr & 3, j = kr >> 2;
    int nh = n >> 6, nt = (n >> 3) & 7, gid = n & 7;
    int pidx = (((((nh * 16 + ks) * 4 + tig) * 8 + gid) * 8) + nt) * 2 + j;
    g_wl32[pidx] = f2tf32(Wl[i]);
    g_wr32[pidx] = f2tf32(Wr[i]);
}

// ---------------- kernel 0: init counters + scan flags ------------------------------
__global__ void k_init() {
    int i = blockIdx.x * blockDim.x + threadIdx.x;
    if (i < N_NODES) {
        g_cnt[i] = 1;
        g_fill[i] = 0;
    }
    if (i < NTILES) {
        g_scan_flag[i] = 0;
    }
}

// ---------------- kernel 1: histogram of destination degrees ------------------------
__global__ __launch_bounds__(256) void k_hist(const int* __restrict__ ei) {
    int e = blockIdx.x * blockDim.x + threadIdx.x;
    if (e < N_EDGES) atomicAdd(&g_cnt[ei[N_EDGES + e]], 1);
}

// ---------------- kernel 2: dual GEMM, mma.sync tf32, m32-per-warp, 128 regs --------
#define XS_PITCH 132
__global__ __launch_bounds__(256, 2) void k_gemm_mma(
    const float* __restrict__ x,
    const float* __restrict__ bl,
    const float* __restrict__ br)
{
    __shared__ uint32_t xs[64 * XS_PITCH];

    int tid = threadIdx.x;
    int nblk = blockIdx.x * 64;

    #pragma unroll
    for (int i = 0; i < 8; i++) {
        int idx = tid + i * 256;
        int r = idx >> 5, c = idx & 31;
        int n = nblk + r;
        float4 v = make_float4(0.f, 0.f, 0.f, 0.f);
        if (n < N_NODES) v = *reinterpret_cast<const float4*>(x + (size_t)n * IN_CH + c * 4);
        uint4 t;
        t.x = f2tf32(v.x); t.y = f2tf32(v.y); t.z = f2tf32(v.z); t.w = f2tf32(v.w);
        *reinterpret_cast<uint4*>(&xs[r * XS_PITCH + c * 4]) = t;
    }
    __syncthreads();

    int wid  = tid >> 5;
    int lane = tid & 31;
    int gid  = lane >> 2;
    int tig  = lane & 3;
    int mat  = wid >> 2;
    int nh   = (wid >> 1) & 1;
    int mth  = wid & 1;

    const uint32_t* W = mat ? g_wr32 : g_wl32;
    const uint32_t* Wbase = W + nh * 16 * 512 + tig * 128 + gid * 16;

    float acc[2][8][4];
    #pragma unroll
    for (int mt = 0; mt < 2; mt++)
        #pragma unroll
        for (int nt = 0; nt < 8; nt++)
            #pragma unroll
            for (int j = 0; j < 4; j++) acc[mt][nt][j] = 0.f;

    int arowA = (mth * 32 + gid) * XS_PITCH;
    int arowB = arowA + 16 * XS_PITCH;
    int nbase = nh * 64;

    #pragma unroll
    for (int ks = 0; ks < 16; ks++) {
        int k0 = ks * 8;
        const uint4* bp = reinterpret_cast<const uint4*>(Wbase + ks * 512);
        uint4 q0 = bp[0];
        uint4 q1 = bp[1];
        uint4 q2 = bp[2];
        uint4 q3 = bp[3];

        #pragma unroll
        for (int mt = 0; mt < 2; mt++) {
            int ar0 = (mt ? arowB : arowA) + k0 + tig;
            int ar1 = ar0 + 8 * XS_PITCH;
            uint32_t a0 = xs[ar0];
            uint32_t a1 = xs[ar1];
            uint32_t a2 = xs[ar0 + 4];
            uint32_t a3 = xs[ar1 + 4];

            asm volatile("mma.sync.aligned.m16n8k8.row.col.f32.tf32.tf32.f32 "
                "{%0,%1,%2,%3}, {%4,%5,%6,%7}, {%8,%9}, {%0,%1,%2,%3};"
                : "+f"(acc[mt][0][0]), "+f"(acc[mt][0][1]), "+f"(acc[mt][0][2]), "+f"(acc[mt][0][3])
                : "r"(a0), "r"(a1), "r"(a2), "r"(a3), "r"(q0.x), "r"(q0.y));
            asm volatile("mma.sync.aligned.m16n8k8.row.col.f32.tf32.tf32.f32 "
                "{%0,%1,%2,%3}, {%4,%5,%6,%7}, {%8,%9}, {%0,%1,%2,%3};"
                : "+f"(acc[mt][1][0]), "+f"(acc[mt][1][1]), "+f"(acc[mt][1][2]), "+f"(acc[mt][1][3])
                : "r"(a0), "r"(a1), "r"(a2), "r"(a3), "r"(q0.z), "r"(q0.w));
            asm volatile("mma.sync.aligned.m16n8k8.row.col.f32.tf32.tf32.f32 "
                "{%0,%1,%2,%3}, {%4,%5,%6,%7}, {%8,%9}, {%0,%1,%2,%3};"
                : "+f"(acc[mt][2][0]), "+f"(acc[mt][2][1]), "+f"(acc[mt][2][2]), "+f"(acc[mt][2][3])
                : "r"(a0), "r"(a1), "r"(a2), "r"(a3), "r"(q1.x), "r"(q1.y));
            asm volatile("mma.sync.aligned.m16n8k8.row.col.f32.tf32.tf32.f32 "
                "{%0,%1,%2,%3}, {%4,%5,%6,%7}, {%8,%9}, {%0,%1,%2,%3};"
                : "+f"(acc[mt][3][0]), "+f"(acc[mt][3][1]), "+f"(acc[mt][3][2]), "+f"(acc[mt][3][3])
                : "r"(a0), "r"(a1), "r"(a2), "r"(a3), "r"(q1.z), "r"(q1.w));
            asm volatile("mma.sync.aligned.m16n8k8.row.col.f32.tf32.tf32.f32 "
                "{%0,%1,%2,%3}, {%4,%5,%6,%7}, {%8,%9}, {%0,%1,%2,%3};"
                : "+f"(acc[mt][4][0]), "+f"(acc[mt][4][1]), "+f"(acc[mt][4][2]), "+f"(acc[mt][4][3])
                : "r"(a0), "r"(a1), "r"(a2), "r"(a3), "r"(q2.x), "r"(q2.y));
            asm volatile("mma.sync.aligned.m16n8k8.row.col.f32.tf32.tf32.f32 "
                "{%0,%1,%2,%3}, {%4,%5,%6,%7}, {%8,%9}, {%0,%1,%2,%3};"
                : "+f"(acc[mt][5][0]), "+f"(acc[mt][5][1]), "+f"(acc[mt][5][2]), "+f"(acc[mt][5][3])
                : "r"(a0), "r"(a1), "r"(a2), "r"(a3), "r"(q2.z), "r"(q2.w));
            asm volatile("mma.sync.aligned.m16n8k8.row.col.f32.tf32.tf32.f32 "
                "{%0,%1,%2,%3}, {%4,%5,%6,%7}, {%8,%9}, {%0,%1,%2,%3};"
                : "+f"(acc[mt][6][0]), "+f"(acc[mt][6][1]), "+f"(acc[mt][6][2]), "+f"(acc[mt][6][3])
                : "r"(a0), "r"(a1), "r"(a2), "r"(a3), "r"(q3.x), "r"(q3.y));
            asm volatile("mma.sync.aligned.m16n8k8.row.col.f32.tf32.tf32.f32 "
                "{%0,%1,%2,%3}, {%4,%5,%6,%7}, {%8,%9}, {%0,%1,%2,%3};"
                : "+f"(acc[mt][7][0]), "+f"(acc[mt][7][1]), "+f"(acc[mt][7][2]), "+f"(acc[mt][7][3])
                : "r"(a0), "r"(a1), "r"(a2), "r"(a3), "r"(q3.z), "r"(q3.w));
        }
    }

    const float* bv = mat ? br : bl;
    float* dst = mat ? g_xr : g_xl;

    #pragma unroll
    for (int mt = 0; mt < 2; mt++) {
        int r0 = nblk + mth * 32 + mt * 16 + gid;
        int r1 = r0 + 8;
        bool ok0 = (r0 < N_NODES), ok1 = (r1 < N_NODES);
        #pragma unroll
        for (int nt = 0; nt < 8; nt++) {
            int c = nbase + nt * 8 + 2 * tig;
            float2 b2 = *reinterpret_cast<const float2*>(bv + c);
            if (ok0) {
                float2 o = make_float2(acc[mt][nt][0] + b2.x, acc[mt][nt][1] + b2.y);
                *reinterpret_cast<float2*>(dst + (size_t)r0 * OUT_CH + c) = o;
            }
            if (ok1) {
                float2 o = make_float2(acc[mt][nt][2] + b2.x, acc[mt][nt][3] + b2.y);
                *reinterpret_cast<float2*>(dst + (size_t)r1 * OUT_CH + c) = o;
            }
        }
    }
}

// ---------------- kernel 3: single-pass exclusive scan ------------------------------
__global__ __launch_bounds__(SCAN_B) void k_scan() {
    __shared__ int warp_excl[16];
    __shared__ int s_total;
    __shared__ int s_prev;

    int t = blockIdx.x, tid = threadIdx.x;
    int i = t * SCAN_B + tid;
    int lane = tid & 31, w = tid >> 5;

    int v = (i < N_NODES) ? g_cnt[i] : 0;

    int inc = v;
    #pragma unroll
    for (int off = 1; off < 32; off <<= 1) {
        int n = __shfl_up_sync(0xFFFFFFFFu, inc, off);
        if (lane >= off) inc += n;
    }
    if (lane == 31) warp_excl[w] = inc;
    __syncthreads();

    if (w == 0) {
        int ws = (lane < 16) ? warp_excl[lane] : 0;
        int wi = ws;
        #pragma unroll
        for (int off = 1; off < 16; off <<= 1) {
            int n = __shfl_up_sync(0xFFFFFFFFu, wi, off);
            if (lane >= off) wi += n;
        }
        if (lane < 16) warp_excl[lane] = wi - ws;
        if (lane == 15) s_total = wi;
    }
    __syncthreads();

    int block_total = s_total;
    int excl_in_block = warp_excl[w] + inc - v;

    if (tid == 0) {
        if (t == 0) {
            g_scan_pref[0] = block_total;
            __threadfence();
            g_scan_flag[0] = 2;
            s_prev = 0;
        } else {
            g_scan_agg[t] = block_total;
            __threadfence();
            g_scan_flag[t] = 1;
            int run = 0;
            int p = t - 1;
            while (true) {
                int f;
                do { f = g_scan_flag[p]; } while (f == 0);
                __threadfence();
                if (f == 2) { run += g_scan_pref[p]; break; }
                run += g_scan_agg[p];
                p--;
            }
            g_scan_pref[t] = run + block_total;
            __threadfence();
            g_scan_flag[t] = 2;
            s_prev = run;
        }
    }
    __syncthreads();

    if (i < N_NODES) g_rowptr[i] = s_prev + excl_in_block;
    if (i == N_NODES - 1) g_rowptr[N_NODES] = s_prev + block_total;
}

// ---------------- kernel 4: fill CSR -------------------------------------------------
__global__ __launch_bounds__(256) void k_fill(const int* __restrict__ ei) {
    int t = blockIdx.x * blockDim.x + threadIdx.x;
    if (t >= NE_TOT) return;
    int src, dst;
    if (t < N_EDGES) { src = ei[t]; dst = ei[N_EDGES + t]; }
    else             { src = dst = t - N_EDGES; }
    int pos = g_rowptr[dst] + atomicAdd(&g_fill[dst], 1);
    g_csr[pos] = src;
}

// ---------------- kernel 5: fused aggregate + SiLU + LayerNorm (4-edge unroll) ------
__global__ __launch_bounds__(256) void k_aggregate(
    const float* __restrict__ att,
    const float* __restrict__ bias,
    const float* __restrict__ gamma,
    const float* __restrict__ beta,
    float* __restrict__ out)
{
    int warp = (blockIdx.x * blockDim.x + threadIdx.x) >> 5;
    int lane = threadIdx.x & 31;
    if (warp >= N_NODES) return;

    float4 a   = *reinterpret_cast<const float4*>(att + lane * 4);
    float4 xr4 = *reinterpret_cast<const float4*>(g_xr + (size_t)warp * OUT_CH + lane * 4);

    int base = g_rowptr[warp];
    int end  = g_rowptr[warp + 1];

    float4 acc = make_float4(0.f, 0.f, 0.f, 0.f);
    float denom = 0.f;

    int k = base;
    for (; k + 3 < end; k += 4) {
        int s0 = g_csr[k];
        int s1 = g_csr[k + 1];
        int s2 = g_csr[k + 2];
        int s3 = g_csr[k + 3];
        float4 v0 = *reinterpret_cast<const float4*>(g_xl + (size_t)s0 * OUT_CH + lane * 4);
        float4 v1 = *reinterpret_cast<const float4*>(g_xl + (size_t)s1 * OUT_CH + lane * 4);
        float4 v2 = *reinterpret_cast<const float4*>(g_xl + (size_t)s2 * OUT_CH + lane * 4);
        float4 v3 = *reinterpret_cast<const float4*>(g_xl + (size_t)s3 * OUT_CH + lane * 4);

        float sc0 = a.x * lrelu(v0.x + xr4.x) + a.y * lrelu(v0.y + xr4.y)
                  + a.z * lrelu(v0.z + xr4.z) + a.w * lrelu(v0.w + xr4.w);
        float sc1 = a.x * lrelu(v1.x + xr4.x) + a.y * lrelu(v1.y + xr4.y)
                  + a.z * lrelu(v1.z + xr4.z) + a.w * lrelu(v1.w + xr4.w);
        float sc2 = a.x * lrelu(v2.x + xr4.x) + a.y * lrelu(v2.y + xr4.y)
                  + a.z * lrelu(v2.z + xr4.z) + a.w * lrelu(v2.w + xr4.w);
        float sc3 = a.x * lrelu(v3.x + xr4.x) + a.y * lrelu(v3.y + xr4.y)
                  + a.z * lrelu(v3.z + xr4.z) + a.w * lrelu(v3.w + xr4.w);

        sc0 += __shfl_xor_sync(0xFFFFFFFFu, sc0, 1);
        sc1 += __shfl_xor_sync(0xFFFFFFFFu, sc1, 1);
        sc2 += __shfl_xor_sync(0xFFFFFFFFu, sc2, 1);
        sc3 += __shfl_xor_sync(0xFFFFFFFFu, sc3, 1);
        sc0 += __shfl_xor_sync(0xFFFFFFFFu, sc0, 2);
        sc1 += __shfl_xor_sync(0xFFFFFFFFu, sc1, 2);
        sc2 += __shfl_xor_sync(0xFFFFFFFFu, sc2, 2);
        sc3 += __shfl_xor_sync(0xFFFFFFFFu, sc3, 2);
        sc0 += __shfl_xor_sync(0xFFFFFFFFu, sc0, 4);
        sc1 += __shfl_xor_sync(0xFFFFFFFFu, sc1, 4);
        sc2 += __shfl_xor_sync(0xFFFFFFFFu, sc2, 4);
        sc3 += __shfl_xor_sync(0xFFFFFFFFu, sc3, 4);

        float w0 = __expf(sc0);
        float w1 = __expf(sc1);
        float w2 = __expf(sc2);
        float w3 = __expf(sc3);
        denom += (w0 + w1) + (w2 + w3);
        acc.x = fmaf(w0, v0.x, fmaf(w1, v1.x, fmaf(w2, v2.x, fmaf(w3, v3.x, acc.x))));
        acc.y = fmaf(w0, v0.y, fmaf(w1, v1.y, fmaf(w2, v2.y, fmaf(w3, v3.y, acc.y))));
        acc.z = fmaf(w0, v0.z, fmaf(w1, v1.z, fmaf(w2, v2.z, fmaf(w3, v3.z, acc.z))));
        acc.w = fmaf(w0, v0.w, fmaf(w1, v1.w, fmaf(w2, v2.w, fmaf(w3, v3.w, acc.w))));
    }
    for (; k < end; k++) {
        int s0 = g_csr[k];
        float4 v0 = *reinterpret_cast<const float4*>(g_xl + (size_t)s0 * OUT_CH + lane * 4);
        float sc0 = a.x * lrelu(v0.x + xr4.x) + a.y * lrelu(v0.y + xr4.y)
                  + a.z * lrelu(v0.z + xr4.z) + a.w * lrelu(v0.w + xr4.w);
        sc0 += __shfl_xor_sync(0xFFFFFFFFu, sc0, 1);
        sc0 += __shfl_xor_sync(0xFFFFFFFFu, sc0, 2);
        sc0 += __shfl_xor_sync(0xFFFFFFFFu, sc0, 4);
        float w0 = __expf(sc0);
        denom += w0;
        acc.x = fmaf(w0, v0.x, acc.x);
        acc.y = fmaf(w0, v0.y, acc.y);
        acc.z = fmaf(w0, v0.z, acc.z);
        acc.w = fmaf(w0, v0.w, acc.w);
    }

    float inv = __frcp_rn(denom);
    float4 b = *reinterpret_cast<const float4*>(bias + lane * 4);
    float4 v;
    v.x = fmaf(acc.x, inv, b.x);
    v.y = fmaf(acc.y, inv, b.y);
    v.z = fmaf(acc.z, inv, b.z);
    v.w = fmaf(acc.w, inv, b.w);

    v.x = v.x / (1.f + __expf(-v.x));
    v.y = v.y / (1.f + __expf(-v.y));
    v.z = v.z / (1.f + __expf(-v.z));
    v.w = v.w / (1.f + __expf(-v.w));

    float sum = v.x + v.y + v.z + v.w;
    float sq  = v.x * v.x + v.y * v.y + v.z * v.z + v.w * v.w;
    #pragma unroll
    for (int off = 16; off; off >>= 1) {
        sum += __shfl_xor_sync(0xFFFFFFFFu, sum, off);
        sq  += __shfl_xor_sync(0xFFFFFFFFu, sq,  off);
    }
    float mu   = sum * (1.f / OUT_CH);
    float var  = sq * (1.f / OUT_CH) - mu * mu;
    float rstd = rsqrtf(var + LN_EPS);

    float4 g  = *reinterpret_cast<const float4*>(gamma + lane * 4);
    float4 be = *reinterpret_cast<const float4*>(beta  + lane * 4);
    float4 r;
    r.x = (v.x - mu) * rstd * g.x + be.x;
    r.y = (v.y - mu) * rstd * g.y + be.y;
    r.z = (v.z - mu) * rstd * g.z + be.z;
    r.w = (v.w - mu) * rstd * g.w + be.w;
    *reinterpret_cast<float4*>(out + (size_t)warp * OUT_CH + lane * 4) = r;
}

// ---------------- launcher: two-stream fork/join (capture-legal) --------------------
extern "C" void kernel_launch(void* const* d_in, const int* in_sizes, int n_in,
                              void* d_out, int out_size)
{
    const float* x    = (const float*)d_in[0];
    const int*   ei   = (const int*)  d_in[1];
    const float* Wl   = (const float*)d_in[2];
    const float* bl   = (const float*)d_in[3];
    const float* Wr   = (const float*)d_in[4];
    const float* br   = (const float*)d_in[5];
    const float* att  = (const float*)d_in[6];
    const float* bias = (const float*)d_in[7];
    const float* gam  = (const float*)d_in[8];
    const float* bet  = (const float*)d_in[9];
    float* out = (float*)d_out;

    static cudaStream_t s2 = nullptr;
    static cudaEvent_t  e_fork = nullptr, e_join = nullptr;
    if (s2 == nullptr) {
        cudaStreamCreateWithFlags(&s2, cudaStreamNonBlocking);
        cudaEventCreateWithFlags(&e_fork, cudaEventDisableTiming);
        cudaEventCreateWithFlags(&e_join, cudaEventDisableTiming);
    }

    cudaEventRecord(e_fork, 0);
    cudaStreamWaitEvent(s2, e_fork, 0);

    // arm B (s2): CSR build
    k_init<<<(N_NODES + 255) / 256, 256, 0, s2>>>();
    k_hist<<<(N_EDGES + 255) / 256, 256, 0, s2>>>(ei);
    k_scan<<<NTILES, SCAN_B, 0, s2>>>();
    k_fill<<<(NE_TOT + 255) / 256, 256, 0, s2>>>(ei);
    cudaEventRecord(e_join, s2);

    // arm A (default): wconv -> GEMM
    k_wconv<<<(IN_CH * OUT_CH + 255) / 256, 256>>>(Wl, Wr);
    k_gemm_mma<<<(N_NODES + 63) / 64, 256>>>(x, bl, br);

    cudaStreamWaitEvent(0, e_join, 0);
    k_aggregate<<<(N_NODES * 32 + 255) / 256, 256>>>(att, bias, gam, bet, out);
}